// round 6
// baseline (speedup 1.0000x reference)
#include <cuda_runtime.h>

// Causal FIR: y[row][t] = sum_{k=0}^{15} b[k] * x[row][t-k], zero init.
// x: [64, 480000] f32, b: [16] f32, y: [64, 480000] f32.
// R5: OUTS=16 traffic model was right (0.75 mem-instr/output) but R4's
// ptxas reg heuristic (39 regs) serialized the loads. Force MLP=8 with
// asm volatile LDG.128s + launch_bounds(256,2); taps back to __ldg
// (the __constant__ memcpy node cost ~3us wall per replay).

#define N_TAPS 16
#define T_LEN 480000
#define BATCH 64
#define OUTS_PER_THREAD 16

#define LDG128(dst, ptr)                                                   \
    asm volatile("ld.global.nc.v4.f32 {%0,%1,%2,%3}, [%4];"                \
                 : "=f"(dst.x), "=f"(dst.y), "=f"(dst.z), "=f"(dst.w)      \
                 : "l"(ptr))

__global__ __launch_bounds__(256, 2) void fir_kernel(
    const float* __restrict__ x,
    const float* __restrict__ b,
    float* __restrict__ y)
{
    const int row = blockIdx.y;
    const int t0  = (blockIdx.x * blockDim.x + threadIdx.x) * OUTS_PER_THREAD;
    if (t0 >= T_LEN) return;

    const float* __restrict__ xr = x + (size_t)row * T_LEN;

    // v[i] = x[t0 - 16 + i], i in [0, 32). t0 % 16 == 0 -> 64B-aligned base.
    // 8 front-batched LDG.128 (asm volatile: ptxas cannot interleave/collapse).
    float v[32];
    if (t0 >= N_TAPS) {
        const float4* p = reinterpret_cast<const float4*>(xr + t0 - 16);
        float4 r0, r1, r2, r3, r4, r5, r6, r7;
        LDG128(r0, p + 0);
        LDG128(r1, p + 1);
        LDG128(r2, p + 2);
        LDG128(r3, p + 3);
        LDG128(r4, p + 4);
        LDG128(r5, p + 5);
        LDG128(r6, p + 6);
        LDG128(r7, p + 7);
        v[0]=r0.x;  v[1]=r0.y;  v[2]=r0.z;  v[3]=r0.w;
        v[4]=r1.x;  v[5]=r1.y;  v[6]=r1.z;  v[7]=r1.w;
        v[8]=r2.x;  v[9]=r2.y;  v[10]=r2.z; v[11]=r2.w;
        v[12]=r3.x; v[13]=r3.y; v[14]=r3.z; v[15]=r3.w;
        v[16]=r4.x; v[17]=r4.y; v[18]=r4.z; v[19]=r4.w;
        v[20]=r5.x; v[21]=r5.y; v[22]=r5.z; v[23]=r5.w;
        v[24]=r6.x; v[25]=r6.y; v[26]=r6.z; v[27]=r6.w;
        v[28]=r7.x; v[29]=r7.y; v[30]=r7.z; v[31]=r7.w;
    } else {
        // Row head (one thread per row, t0 == 0): zero-padded register.
        #pragma unroll
        for (int i = 0; i < 32; i++) {
            int idx = t0 - 16 + i;
            v[i] = (idx >= 0) ? xr[idx] : 0.0f;
        }
    }

    // Taps: uniform-address, warp-broadcast, L1-resident after warmup.
    float taps[N_TAPS];
    #pragma unroll
    for (int k = 0; k < N_TAPS; k++) taps[k] = __ldg(b + k);

    // y[t0+j] = sum_k taps[k] * v[16 + j - k].
    // Compute+store in groups of 4 so the acc live-set stays at 4 regs.
    float* __restrict__ yr = y + (size_t)row * T_LEN + t0;
    #pragma unroll
    for (int g = 0; g < 4; g++) {
        float a0 = 0.0f, a1 = 0.0f, a2 = 0.0f, a3 = 0.0f;
        #pragma unroll
        for (int k = 0; k < N_TAPS; k++) {
            const float t = taps[k];
            a0 = fmaf(t, v[16 + 4*g + 0 - k], a0);
            a1 = fmaf(t, v[16 + 4*g + 1 - k], a1);
            a2 = fmaf(t, v[16 + 4*g + 2 - k], a2);
            a3 = fmaf(t, v[16 + 4*g + 3 - k], a3);
        }
        float4 o;
        o.x = a0; o.y = a1; o.z = a2; o.w = a3;
        reinterpret_cast<float4*>(yr)[g] = o;
    }
}

extern "C" void kernel_launch(void* const* d_in, const int* in_sizes, int n_in,
                              void* d_out, int out_size)
{
    const float* x = (const float*)d_in[0];
    const float* b = (const float*)d_in[1];
    float* y = (float*)d_out;

    const int threads = 256;
    const int threads_per_row = T_LEN / OUTS_PER_THREAD;          // 30000
    dim3 grid((threads_per_row + threads - 1) / threads, BATCH);  // (118, 64)
    fir_kernel<<<grid, threads>>>(x, b, y);
}

// round 7
// speedup vs baseline: 1.3461x; 1.3461x over previous
#include <cuda_runtime.h>

// Causal FIR: y[row][t] = sum_{k=0}^{15} b[k] * x[row][t-k], zero init.
// x: [64, 480000] f32, b: [16] f32, y: [64, 480000] f32.
// R6: back to the proven R3 operating point (OUTS=8, natural codegen,
// occ ~50-60%). Single change: taps via __constant__ (LDC, constant port)
// instead of 16 per-thread __ldg's -- removes 2/3 of L1tex LSU
// instructions and 1/3 of wavefronts, frees ~16 regs.

#define N_TAPS 16
#define T_LEN 480000
#define BATCH 64
#define OUTS_PER_THREAD 8

__constant__ float c_taps[N_TAPS];

__global__ __launch_bounds__(256) void fir_kernel(
    const float* __restrict__ x,
    float* __restrict__ y)
{
    const int row = blockIdx.y;
    const int t0  = (blockIdx.x * blockDim.x + threadIdx.x) * OUTS_PER_THREAD;
    if (t0 >= T_LEN) return;

    const float* __restrict__ xr = x + (size_t)row * T_LEN;

    // v[i] = x[t0 - 16 + i], i in [0, 24). t0 % 8 == 0 so xr + t0 - 16 is
    // 32B-aligned: 6 aligned float4 loads, front-batched (MLP=6).
    float v[24];
    if (t0 >= N_TAPS) {
        const float4* __restrict__ p =
            reinterpret_cast<const float4*>(xr + t0 - 16);
        #pragma unroll
        for (int i = 0; i < 6; i++) {
            float4 f = p[i];
            v[4*i + 0] = f.x;
            v[4*i + 1] = f.y;
            v[4*i + 2] = f.z;
            v[4*i + 3] = f.w;
        }
    } else {
        // Row head: zero-padded shift register. Only 2 threads/row (t0=0,8).
        #pragma unroll
        for (int i = 0; i < 24; i++) {
            int idx = t0 - 16 + i;
            v[i] = (idx >= 0) ? xr[idx] : 0.0f;
        }
    }

    // y[t0+j] = sum_k c_taps[k] * v[16 + j - k]; taps via constant port.
    float acc[OUTS_PER_THREAD];
    #pragma unroll
    for (int j = 0; j < OUTS_PER_THREAD; j++) {
        float a = 0.0f;
        #pragma unroll
        for (int k = 0; k < N_TAPS; k++) {
            a = fmaf(c_taps[k], v[16 + j - k], a);
        }
        acc[j] = a;
    }

    float* yr = y + (size_t)row * T_LEN + t0;
    float4 o0, o1;
    o0.x = acc[0]; o0.y = acc[1]; o0.z = acc[2]; o0.w = acc[3];
    o1.x = acc[4]; o1.y = acc[5]; o1.z = acc[6]; o1.w = acc[7];
    reinterpret_cast<float4*>(yr)[0] = o0;
    reinterpret_cast<float4*>(yr)[1] = o1;
}

extern "C" void kernel_launch(void* const* d_in, const int* in_sizes, int n_in,
                              void* d_out, int out_size)
{
    const float* x = (const float*)d_in[0];
    const float* b = (const float*)d_in[1];
    float* y = (float*)d_out;

    // Taps -> constant bank (64 B D2D async copy; graph-capturable).
    cudaMemcpyToSymbolAsync(c_taps, b, N_TAPS * sizeof(float), 0,
                            cudaMemcpyDeviceToDevice, 0);

    const int threads = 256;
    const int threads_per_row = T_LEN / OUTS_PER_THREAD;          // 60000
    dim3 grid((threads_per_row + threads - 1) / threads, BATCH);  // (235, 64)
    fir_kernel<<<grid, threads>>>(x, y);
}